// round 2
// baseline (speedup 1.0000x reference)
#include <cuda_runtime.h>
#include <math.h>

#define BB 32
#define NN 32768
#define DD 128
#define TN 128
#define NBLK (NN / TN)   // 256

// Scratch (no allocations allowed in kernel_launch)
__device__ float g_logits[(size_t)BB * NN];       // 4 MB
__device__ float g_m[BB];
__device__ float g_z[BB];
__device__ float g_partial[NBLK][BB * DD];        // 4 MB

// ---------------------------------------------------------------------------
// Kernel A: logits[b][n] = c1_b * (x_b . y_n) - c2_b * |y_n|^2
// Grid: NBLK blocks x 256 threads. Tile: 32 b x 128 n, k-chunked by 32.
// ---------------------------------------------------------------------------
__global__ __launch_bounds__(256) void logits_kernel(
    const float* __restrict__ x,       // [B, D]
    const float* __restrict__ alphas,  // [B]
    const float* __restrict__ y)       // [N, D]
{
    __shared__ float xs[BB][DD];       // 16 KB
    __shared__ float ys[TN][33];       // ~16.9 KB, pitch 33 => conflict-free
    __shared__ float nnorm[TN];

    const int tid  = threadIdx.x;
    const int lane = tid & 31;
    const int warp = tid >> 5;
    const int nbase = blockIdx.x * TN;

    // Load x [32,128] into smem (coalesced)
    for (int i = tid; i < BB * DD; i += 256) xs[i >> 7][i & 127] = x[i];
    if (tid < TN) nnorm[tid] = 0.f;

    const int ng = lane;        // n-group: thread covers n = ng + 32*j
    const int b0 = warp * 4;    // b-group: 4 consecutive b

    float acc[4][4];
#pragma unroll
    for (int i = 0; i < 4; i++)
#pragma unroll
        for (int j = 0; j < 4; j++) acc[i][j] = 0.f;

    for (int kc = 0; kc < DD; kc += 32) {
        __syncthreads();
        // Load y chunk [TN][32] (coalesced: lanes cover k), fuse |y|^2 partial
#pragma unroll
        for (int it = 0; it < TN / 8; it++) {
            const int n = warp + it * 8;
            float v = y[(size_t)(nbase + n) * DD + kc + lane];
            ys[n][lane] = v;
            float s = v * v;
#pragma unroll
            for (int o = 16; o > 0; o >>= 1) s += __shfl_xor_sync(0xffffffffu, s, o);
            if (lane == 0) nnorm[n] += s;
        }
        __syncthreads();

#pragma unroll
        for (int k = 0; k < 32; k++) {
            float yv[4];
#pragma unroll
            for (int j = 0; j < 4; j++) yv[j] = ys[ng + 32 * j][k];
#pragma unroll
            for (int i = 0; i < 4; i++) {
                const float xv = xs[b0 + i][kc + k];
#pragma unroll
                for (int j = 0; j < 4; j++) acc[i][j] = fmaf(xv, yv[j], acc[i][j]);
            }
        }
    }
    __syncthreads();

#pragma unroll
    for (int i = 0; i < 4; i++) {
        const int b = b0 + i;
        const float a   = alphas[b];
        const float var = 1.f - a;
        const float c1  = sqrtf(a) / var;
        const float c2  = a / (2.f * var);
#pragma unroll
        for (int j = 0; j < 4; j++) {
            const int n = ng + 32 * j;
            g_logits[(size_t)b * NN + nbase + n] = c1 * acc[i][j] - c2 * nnorm[n];
        }
    }
}

// ---------------------------------------------------------------------------
// Kernel B: per-b max and sum of exp(l - m). Grid: 32 blocks x 512 threads.
// ---------------------------------------------------------------------------
__global__ __launch_bounds__(512) void softmax_stats_kernel()
{
    const int b   = blockIdx.x;
    const int tid = threadIdx.x;
    const float* l = &g_logits[(size_t)b * NN];

    __shared__ float red[16];
    __shared__ float bcast;

    float m = -1e30f;
    for (int i = tid; i < NN; i += 512) m = fmaxf(m, l[i]);
#pragma unroll
    for (int o = 16; o > 0; o >>= 1) m = fmaxf(m, __shfl_xor_sync(0xffffffffu, m, o));
    if ((tid & 31) == 0) red[tid >> 5] = m;
    __syncthreads();
    if (tid == 0) {
        float v = red[0];
        for (int w = 1; w < 16; w++) v = fmaxf(v, red[w]);
        bcast = v;
    }
    __syncthreads();
    m = bcast;

    float z = 0.f;
    for (int i = tid; i < NN; i += 512) z += expf(l[i] - m);
#pragma unroll
    for (int o = 16; o > 0; o >>= 1) z += __shfl_xor_sync(0xffffffffu, z, o);
    __syncthreads();
    if ((tid & 31) == 0) red[tid >> 5] = z;
    __syncthreads();
    if (tid == 0) {
        float s = 0.f;
        for (int w = 0; w < 16; w++) s += red[w];
        g_m[b] = m;
        g_z[b] = s;
    }
}

// ---------------------------------------------------------------------------
// Kernel C: partial S[b][d] = sum_{n in chunk} exp(l-m) * y[n][d]
// Grid: NBLK blocks x 256 threads. Tile: 32 b x 128 d, n-chunked by 32.
// ---------------------------------------------------------------------------
__global__ __launch_bounds__(256) void wsum_kernel(const float* __restrict__ y)
{
    __shared__ float ps[BB][TN];       // 16 KB
    __shared__ float ys[32][129];      // 16.5 KB, pitch 129

    const int tid   = threadIdx.x;
    const int nbase = blockIdx.x * TN;

    // Unnormalized softmax weights for this n-chunk
    for (int t = tid; t < BB * TN; t += 256) {
        const int b = t >> 7, n = t & 127;
        ps[b][n] = expf(g_logits[(size_t)b * NN + nbase + n] - g_m[b]);
    }

    const int dg = tid & 31;           // d = dg + 32*j
    const int b0 = (tid >> 5) * 4;

    float acc[4][4];
#pragma unroll
    for (int i = 0; i < 4; i++)
#pragma unroll
        for (int j = 0; j < 4; j++) acc[i][j] = 0.f;

    for (int nc = 0; nc < TN; nc += 32) {
        __syncthreads();
        for (int t = tid; t < 32 * DD; t += 256) {
            const int n = t >> 7, d = t & 127;
            ys[n][d] = y[(size_t)(nbase + nc + n) * DD + d];
        }
        __syncthreads();

#pragma unroll
        for (int nn = 0; nn < 32; nn++) {
            float yv[4];
#pragma unroll
            for (int j = 0; j < 4; j++) yv[j] = ys[nn][dg + 32 * j];
#pragma unroll
            for (int i = 0; i < 4; i++) {
                const float pv = ps[b0 + i][nc + nn];
#pragma unroll
                for (int j = 0; j < 4; j++) acc[i][j] = fmaf(pv, yv[j], acc[i][j]);
            }
        }
    }

#pragma unroll
    for (int i = 0; i < 4; i++)
#pragma unroll
        for (int j = 0; j < 4; j++)
            g_partial[blockIdx.x][(b0 + i) * DD + dg + 32 * j] = acc[i][j];
}

// ---------------------------------------------------------------------------
// Kernel D: reduce partials, out = (x - sqrt(a)*x0) / sqrt(var)
// Grid: 32 blocks x 128 threads.
// ---------------------------------------------------------------------------
__global__ __launch_bounds__(128) void finalize_kernel(
    const float* __restrict__ x,
    const float* __restrict__ alphas,
    float* __restrict__ out)
{
    const int b = blockIdx.x;
    const int d = threadIdx.x;
    float s = 0.f;
#pragma unroll 8
    for (int c = 0; c < NBLK; c++) s += g_partial[c][b * DD + d];

    const float a   = alphas[b];
    const float var = 1.f - a;
    const float x0  = s / g_z[b];
    out[b * DD + d] = (x[b * DD + d] - sqrtf(a) * x0) / sqrtf(var);
}

// ---------------------------------------------------------------------------
extern "C" void kernel_launch(void* const* d_in, const int* in_sizes, int n_in,
                              void* d_out, int out_size)
{
    const float* inputs = (const float*)d_in[0];   // [B, D]
    const float* alphas = (const float*)d_in[1];   // [B]
    const float* data   = (const float*)d_in[2];   // [N, D]
    float* out = (float*)d_out;                    // [B, D]

    logits_kernel<<<NBLK, 256>>>(inputs, alphas, data);
    softmax_stats_kernel<<<BB, 512>>>();
    wsum_kernel<<<NBLK, 256>>>(data);
    finalize_kernel<<<BB, DD>>>(inputs, alphas, out);
}

// round 3
// speedup vs baseline: 1.4710x; 1.4710x over previous
#include <cuda_runtime.h>
#include <math.h>

#define BB 32
#define NN 32768
#define DD 128
#define TN 128
#define NBLK (NN / TN)   // 256
#define YP 129           // ys smem pitch (conflict-free both access patterns)

// Scratch (no allocations allowed)
__device__ float g_cm[NBLK][BB];                  // per-chunk max
__device__ float g_cz[NBLK][BB];                  // per-chunk sum(exp)
__device__ float g_partial[NBLK][BB * DD];        // per-chunk unnormalized x0 partials (4 MB)

// smem floats: xs 32*128=4096, ys 128*129=16512, ps 32*128=4096, nrm 128
#define SMEM_FLOATS (BB*DD + TN*YP + BB*TN + TN)
#define SMEM_BYTES  (SMEM_FLOATS * 4)             // 99328 B -> 2 CTAs/SM

extern __shared__ float s_mem[];

// ---------------------------------------------------------------------------
// Fused kernel: per 128-n chunk:
//   logits l[b][n] = c1_b*(x_b . y_n) - c2_b*|y_n|^2      (GEMM1, k contracted)
//   chunk softmax stats m_c, z_c; p = exp(l - m_c)
//   S_c[b][d] = sum_n p[b][n] * y[n][d]                   (GEMM2, n contracted)
// Grid: 256 blocks x 256 threads. Warp w owns b = 4w..4w+3.
// ---------------------------------------------------------------------------
__global__ __launch_bounds__(256) void fused_kernel(
    const float* __restrict__ x,       // [B, D]
    const float* __restrict__ alphas,  // [B]
    const float* __restrict__ y)       // [N, D]
{
    float* xs  = s_mem;                // [32][128]
    float* ys  = xs + BB * DD;         // [128][YP]
    float* ps  = ys + TN * YP;         // [32][128]
    float* nrm = ps + BB * TN;         // [128]

    const int tid  = threadIdx.x;
    const int lane = tid & 31;
    const int warp = tid >> 5;
    const int blk  = blockIdx.x;
    const int nbase = blk * TN;

    // ---- load x [32,128] and y tile [128,128] (both coalesced) ----
    for (int i = tid; i < BB * DD; i += 256) xs[i] = x[i];
    for (int t = tid; t < TN * DD; t += 256) {
        const int n = t >> 7, d = t & 127;
        ys[n * YP + d] = y[(size_t)(nbase + n) * DD + d];
    }
    __syncthreads();

    // ---- row norms |y_n|^2 : warp w handles rows w, w+8, ... ----
    for (int n = warp; n < TN; n += 8) {
        float s = 0.f;
#pragma unroll
        for (int m = 0; m < 4; m++) {
            const float v = ys[n * YP + lane + 32 * m];
            s = fmaf(v, v, s);
        }
#pragma unroll
        for (int o = 16; o > 0; o >>= 1) s += __shfl_xor_sync(0xffffffffu, s, o);
        if (lane == 0) nrm[n] = s;
    }
    __syncthreads();

    const int ng = lane;        // thread's n = ng + 32*j
    const int b0 = warp * 4;    // thread's b = b0 + i

    // ---- GEMM1: acc[i][j] = x_{b0+i} . y_{ng+32j} ----
    float acc[4][4] = {};
#pragma unroll 4
    for (int k = 0; k < DD; k++) {
        float yv[4];
#pragma unroll
        for (int j = 0; j < 4; j++) yv[j] = ys[(ng + 32 * j) * YP + k];
#pragma unroll
        for (int i = 0; i < 4; i++) {
            const float xv = xs[(b0 + i) * DD + k];   // broadcast across lanes
#pragma unroll
            for (int j = 0; j < 4; j++) acc[i][j] = fmaf(xv, yv[j], acc[i][j]);
        }
    }

    // ---- chunk softmax per b (warp-private rows of ps) ----
    float nv[4];
#pragma unroll
    for (int j = 0; j < 4; j++) nv[j] = nrm[ng + 32 * j];

#pragma unroll
    for (int i = 0; i < 4; i++) {
        const int b = b0 + i;
        const float a   = alphas[b];
        const float var = 1.f - a;
        const float c1  = sqrtf(a) / var;
        const float c2  = a / (2.f * var);
        float l[4];
#pragma unroll
        for (int j = 0; j < 4; j++) l[j] = c1 * acc[i][j] - c2 * nv[j];

        float mi = fmaxf(fmaxf(l[0], l[1]), fmaxf(l[2], l[3]));
#pragma unroll
        for (int o = 16; o > 0; o >>= 1)
            mi = fmaxf(mi, __shfl_xor_sync(0xffffffffu, mi, o));

        float zi = 0.f;
#pragma unroll
        for (int j = 0; j < 4; j++) {
            const float p = expf(l[j] - mi);
            ps[b * TN + ng + 32 * j] = p;
            zi += p;
        }
#pragma unroll
        for (int o = 16; o > 0; o >>= 1) zi += __shfl_xor_sync(0xffffffffu, zi, o);

        if (lane == 0) { g_cm[blk][b] = mi; g_cz[blk][b] = zi; }
    }
    __syncwarp();   // ps rows are warp-private; no block sync needed

    // ---- GEMM2: acc2[i][j] = sum_n p[b0+i][n] * y[n][lane+32j] ----
    float acc2[4][4] = {};
#pragma unroll 4
    for (int n = 0; n < TN; n++) {
        float yv[4];
#pragma unroll
        for (int j = 0; j < 4; j++) yv[j] = ys[n * YP + lane + 32 * j];
#pragma unroll
        for (int i = 0; i < 4; i++) {
            const float pv = ps[(b0 + i) * TN + n];   // broadcast
#pragma unroll
            for (int j = 0; j < 4; j++) acc2[i][j] = fmaf(pv, yv[j], acc2[i][j]);
        }
    }

#pragma unroll
    for (int i = 0; i < 4; i++)
#pragma unroll
        for (int j = 0; j < 4; j++)
            g_partial[blk][(b0 + i) * DD + lane + 32 * j] = acc2[i][j];
}

// ---------------------------------------------------------------------------
// Finalize: global softmax combine + output.
// Grid: 32 blocks (one per b) x 1024 threads (8 chunk-groups x 128 d).
// ---------------------------------------------------------------------------
__global__ __launch_bounds__(1024) void finalize_kernel(
    const float* __restrict__ x,
    const float* __restrict__ alphas,
    float* __restrict__ out)
{
    __shared__ float red[32];
    __shared__ float wv[NBLK];
    __shared__ float sgrp[8][DD];
    __shared__ float m_sh, z_sh;

    const int b    = blockIdx.x;
    const int tid  = threadIdx.x;
    const int lane = tid & 31;
    const int warp = tid >> 5;

    // 1. global max over 256 chunk maxes
    float m = (tid < NBLK) ? g_cm[tid][b] : -1e30f;
#pragma unroll
    for (int o = 16; o > 0; o >>= 1) m = fmaxf(m, __shfl_xor_sync(0xffffffffu, m, o));
    if (lane == 0) red[warp] = m;
    __syncthreads();
    if (tid == 0) {
        float v = red[0];
        for (int w = 1; w < 32; w++) v = fmaxf(v, red[w]);
        m_sh = v;
    }
    __syncthreads();
    const float M = m_sh;

    // 2. rescale weights w_c = exp(m_c - M); z = sum z_c * w_c
    float zp = 0.f;
    if (tid < NBLK) {
        const float w = expf(g_cm[tid][b] - M);
        wv[tid] = w;
        zp = g_cz[tid][b] * w;
    }
#pragma unroll
    for (int o = 16; o > 0; o >>= 1) zp += __shfl_xor_sync(0xffffffffu, zp, o);
    __syncthreads();          // wv visible; reuse red
    if (lane == 0) red[warp] = zp;
    __syncthreads();
    if (tid == 0) {
        float s = 0.f;
        for (int w = 0; w < 32; w++) s += red[w];
        z_sh = s;
    }
    __syncthreads();

    // 3. S[b][d] = sum_c S_c[b][d] * w_c   (coalesced, MLP-8)
    const int d  = tid & 127;
    const int cg = tid >> 7;          // 0..7
    float s = 0.f;
#pragma unroll 8
    for (int c = cg; c < NBLK; c += 8)
        s += g_partial[c][b * DD + d] * wv[c];
    sgrp[cg][d] = s;
    __syncthreads();

    if (tid < DD) {
        float t = 0.f;
#pragma unroll
        for (int g = 0; g < 8; g++) t += sgrp[g][tid];
        const float a   = alphas[b];
        const float var = 1.f - a;
        const float x0  = t / z_sh;
        out[b * DD + tid] = (x[b * DD + tid] - sqrtf(a) * x0) / sqrtf(var);
    }
}

// ---------------------------------------------------------------------------
extern "C" void kernel_launch(void* const* d_in, const int* in_sizes, int n_in,
                              void* d_out, int out_size)
{
    const float* inputs = (const float*)d_in[0];   // [B, D]
    const float* alphas = (const float*)d_in[1];   // [B]
    const float* data   = (const float*)d_in[2];   // [N, D]
    float* out = (float*)d_out;                    // [B, D]

    cudaFuncSetAttribute(fused_kernel,
                         cudaFuncAttributeMaxDynamicSharedMemorySize, SMEM_BYTES);

    fused_kernel<<<NBLK, 256, SMEM_BYTES>>>(inputs, alphas, data);
    finalize_kernel<<<BB, 1024>>>(inputs, alphas, out);
}

// round 7
// speedup vs baseline: 1.5630x; 1.0626x over previous
#include <cuda_runtime.h>
#include <math.h>

#define BB 32
#define NN 32768
#define DD 128
#define TN 128
#define NBLK (NN / TN)   // 256
#define YP 129           // ys pitch: conflict-free for both [n][k] and [n][d] walks
#define XP 34            // xsT/psT pitch: even (8B-aligned float2), 2-way on stores only
#define NSLICE 8

typedef unsigned long long u64;

// Packed fp32x2 ops (sm_103a FFMA2 — PTX-only, ptxas won't auto-fuse)
#define FMA2(d, a, b, c) \
    asm("fma.rn.f32x2 %0, %1, %2, %3;" : "=l"(d) : "l"(a), "l"(b), "l"(c))
#define DUP2(d, v) \
    asm("mov.b64 %0, {%1, %1};" : "=l"(d) : "r"(__float_as_uint(v)))
#define UNPK2(lo, hi, v) \
    asm("mov.b64 {%0, %1}, %2;" : "=f"(lo), "=f"(hi) : "l"(v))

// Scratch
__device__ float g_cm[BB][NBLK];                  // per-chunk max   (transposed: coalesced reads)
__device__ float g_cz[BB][NBLK];                  // per-chunk sum(exp)
__device__ float g_partial[NBLK][BB * DD];        // per-chunk unnormalized partials (4 MB)
__device__ float g_p2[NSLICE][BB * DD];           // slice-reduced partials (128 KB)

// smem: ys 128*129 | xsT 128*34 | psT 128*34 | nrm 128
#define SM_YS   0
#define SM_XST  (TN * YP)                 // 16512
#define SM_PST  (SM_XST + DD * XP)        // 20864
#define SM_NRM  (SM_PST + TN * XP)        // 25216
#define SMEM_FLOATS (SM_NRM + TN)         // 25344
#define SMEM_BYTES  (SMEM_FLOATS * 4)     // 101376 B -> 2 CTAs/SM

extern __shared__ float s_mem[];

// ---------------------------------------------------------------------------
// Fused: per 128-n chunk: logits GEMM -> chunk softmax -> weighted-sum GEMM.
// Grid: 256 blocks x 256 threads. Warp w owns b = 4w..4w+3 (as 2 packed pairs).
// ---------------------------------------------------------------------------
__global__ __launch_bounds__(256) void fused_kernel(
    const float* __restrict__ x,       // [B, D]
    const float* __restrict__ alphas,  // [B]
    const float* __restrict__ y)       // [N, D]
{
    float* ys  = s_mem + SM_YS;        // [128][YP]  y tile, n-major
    float* xsT = s_mem + SM_XST;       // [128][XP]  x transposed: [k][b]
    float* psT = s_mem + SM_PST;       // [128][XP]  p transposed: [n][b]
    float* nrm = s_mem + SM_NRM;       // [128]

    const int tid  = threadIdx.x;
    const int lane = tid & 31;
    const int warp = tid >> 5;
    const int blk  = blockIdx.x;
    const int nbase = blk * TN;

    // x -> xsT[k][b] (coalesced read; 2-way-conflict store, one-time cost)
    for (int t = tid; t < BB * DD; t += 256) {
        const int b = t >> 7, d = t & 127;
        xsT[d * XP + b] = x[t];
    }
    // y tile (coalesced)
    for (int t = tid; t < TN * DD; t += 256) {
        const int n = t >> 7, d = t & 127;
        ys[n * YP + d] = y[(size_t)(nbase + n) * DD + d];
    }
    __syncthreads();

    // |y_n|^2
    for (int n = warp; n < TN; n += 8) {
        float s = 0.f;
#pragma unroll
        for (int m = 0; m < 4; m++) {
            const float v = ys[n * YP + lane + 32 * m];
            s = fmaf(v, v, s);
        }
#pragma unroll
        for (int o = 16; o > 0; o >>= 1) s += __shfl_xor_sync(0xffffffffu, s, o);
        if (lane == 0) nrm[n] = s;
    }
    __syncthreads();

    const int b0 = warp * 4;   // even: b-pairs (b0,b0+1), (b0+2,b0+3)

    // ---- GEMM1 (packed over b-pairs): acc[ip][j] = {x_{b0+2ip}, x_{b0+2ip+1}} . y_{lane+32j}
    u64 acc[2][4] = {};
#pragma unroll 4
    for (int k = 0; k < DD; k++) {
        const u64 xv0 = *reinterpret_cast<const u64*>(&xsT[k * XP + b0]);     // bcast LDS.64
        const u64 xv1 = *reinterpret_cast<const u64*>(&xsT[k * XP + b0 + 2]);
#pragma unroll
        for (int j = 0; j < 4; j++) {
            u64 yd; DUP2(yd, ys[(lane + 32 * j) * YP + k]);
            FMA2(acc[0][j], xv0, yd, acc[0][j]);
            FMA2(acc[1][j], xv1, yd, acc[1][j]);
        }
    }

    float dots[4][4];
#pragma unroll
    for (int ip = 0; ip < 2; ip++)
#pragma unroll
        for (int j = 0; j < 4; j++)
            UNPK2(dots[2 * ip][j], dots[2 * ip + 1][j], acc[ip][j]);

    // ---- chunk softmax per b (warp-private columns of psT) ----
    float nv[4];
#pragma unroll
    for (int j = 0; j < 4; j++) nv[j] = nrm[lane + 32 * j];

#pragma unroll
    for (int i = 0; i < 4; i++) {
        const int b = b0 + i;
        const float a   = alphas[b];
        const float var = 1.f - a;
        const float c1  = sqrtf(a) / var;
        const float c2  = a / (2.f * var);
        float l[4];
#pragma unroll
        for (int j = 0; j < 4; j++) l[j] = c1 * dots[i][j] - c2 * nv[j];

        float mi = fmaxf(fmaxf(l[0], l[1]), fmaxf(l[2], l[3]));
#pragma unroll
        for (int o = 16; o > 0; o >>= 1)
            mi = fmaxf(mi, __shfl_xor_sync(0xffffffffu, mi, o));

        float zi = 0.f;
#pragma unroll
        for (int j = 0; j < 4; j++) {
            const float p = __expf(l[j] - mi);
            psT[(lane + 32 * j) * XP + b] = p;
            zi += p;
        }
#pragma unroll
        for (int o = 16; o > 0; o >>= 1) zi += __shfl_xor_sync(0xffffffffu, zi, o);

        if (lane == 0) { g_cm[b][blk] = mi; g_cz[b][blk] = zi; }
    }
    __syncwarp();   // psT columns b0..b0+3 are warp-private

    // ---- GEMM2 (packed over b-pairs): acc2[ip][j] = sum_n {p_{b0+2ip},p_{b0+2ip+1}}[n] * y[n][lane+32j]
    u64 acc2[2][4] = {};
#pragma unroll 4
    for (int n = 0; n < TN; n++) {
        const u64 pv0 = *reinterpret_cast<const u64*>(&psT[n * XP + b0]);     // bcast LDS.64
        const u64 pv1 = *reinterpret_cast<const u64*>(&psT[n * XP + b0 + 2]);
#pragma unroll
        for (int j = 0; j < 4; j++) {
            u64 yd; DUP2(yd, ys[n * YP + lane + 32 * j]);
            FMA2(acc2[0][j], pv0, yd, acc2[0][j]);
            FMA2(acc2[1][j], pv1, yd, acc2[1][j]);
        }
    }

#pragma unroll
    for (int ip = 0; ip < 2; ip++)
#pragma unroll
        for (int j = 0; j < 4; j++) {
            float lo, hi;
            UNPK2(lo, hi, acc2[ip][j]);
            g_partial[blk][(b0 + 2 * ip)     * DD + lane + 32 * j] = lo;
            g_partial[blk][(b0 + 2 * ip + 1) * DD + lane + 32 * j] = hi;
        }
}

// ---------------------------------------------------------------------------
// Reduce: 256 blocks (b x 8 slices) x 256 threads.
// Each block: compute global max + weights (L2-hot stats), reduce 32 chunks.
// ---------------------------------------------------------------------------
__global__ __launch_bounds__(256) void reduce_kernel()
{
    const int slice = blockIdx.x & 7;
    const int b     = blockIdx.x >> 3;
    const int tid   = threadIdx.x;
    const int lane  = tid & 31;
    const int warp  = tid >> 5;

    __shared__ float wv[NBLK];
    __shared__ float red[8];
    __shared__ float part[2][DD];
    __shared__ float Msh;

    // global max over 256 chunk maxes (coalesced)
    const float cm = g_cm[b][tid];
    float m = cm;
#pragma unroll
    for (int o = 16; o > 0; o >>= 1) m = fmaxf(m, __shfl_xor_sync(0xffffffffu, m, o));
    if (lane == 0) red[warp] = m;
    __syncthreads();
    if (tid == 0) {
        float v = red[0];
        for (int w = 1; w < 8; w++) v = fmaxf(v, red[w]);
        Msh = v;
    }
    __syncthreads();

    wv[tid] = __expf(cm - Msh);
    __syncthreads();

    // weighted reduce of this slice's 32 chunks (coalesced, MLP-16)
    const int d = tid & 127;
    const int g = tid >> 7;    // 0,1
    float s = 0.f;
#pragma unroll
    for (int i = 0; i < 16; i++) {
        const int c = slice * 32 + g + 2 * i;
        s += g_partial[c][b * DD + d] * wv[c];
    }
    part[g][d] = s;
    __syncthreads();
    if (tid < DD) g_p2[slice][b * DD + tid] = part[0][tid] + part[1][tid];
}

// ---------------------------------------------------------------------------
// Final: 32 blocks x 128 threads. Z recompute + 8-slice sum + output.
// ---------------------------------------------------------------------------
__global__ __launch_bounds__(128) void final_kernel(
    const float* __restrict__ x,
    const float* __restrict__ alphas,
    float* __restrict__ out)
{
    const int b    = blockIdx.x;
    const int tid  = threadIdx.x;
    const int lane = tid & 31;
    const int warp = tid >> 5;

    __shared__ float red[4];
    __shared__ float Msh, Zsh;

    const float cm0 = g_cm[b][tid], cm1 = g_cm[b][tid + 128];
    float m = fmaxf(cm0, cm1);
#pragma unroll
    for (int o = 16; o > 0; o >>= 1) m = fmaxf(m, __shfl_xor_sync(0xffffffffu, m, o));
    if (lane == 0) red[warp] = m;
    __syncthreads();
    if (tid == 0) Msh = fmaxf(fmaxf(red[0], red[1]), fmaxf(red[2], red[3]));
    __syncthreads();
    const float M = Msh;

    float z = g_cz[b][tid] * __expf(cm0 - M) + g_cz[b][tid + 128] * __expf(cm1 - M);
#pragma unroll
    for (int o = 16; o > 0; o >>= 1) z += __shfl_xor_sync(0xffffffffu, z, o);
    __syncthreads();
    if (lane == 0) red[warp] = z;
    __syncthreads();
    if (tid == 0) Zsh = red[0] + red[1] + red[2] + red[3];
    __syncthreads();

    float s = 0.f;
#pragma unroll
    for (int c = 0; c < NSLICE; c++) s += g_p2[c][b * DD + tid];

    const float a   = alphas[b];
    const float var = 1.f - a;
    const float x0  = s / Zsh;
    out[b * DD + tid] = (x[b * DD + tid] - sqrtf(a) * x0) / sqrtf(var);
}

// ---------------------------------------------------------------------------
extern "C" void kernel_launch(void* const* d_in, const int* in_sizes, int n_in,
                              void* d_out, int out_size)
{
    const float* inputs = (const float*)d_in[0];   // [B, D]
    const float* alphas = (const float*)d_in[1];   // [B]
    const float* data   = (const float*)d_in[2];   // [N, D]
    float* out = (float*)d_out;                    // [B, D]

    cudaFuncSetAttribute(fused_kernel,
                         cudaFuncAttributeMaxDynamicSharedMemorySize, SMEM_BYTES);

    fused_kernel<<<NBLK, 256, SMEM_BYTES>>>(inputs, alphas, data);
    reduce_kernel<<<BB * NSLICE, 256>>>();
    final_kernel<<<BB, DD>>>(inputs, alphas, out);
}

// round 8
// speedup vs baseline: 1.7827x; 1.1405x over previous
#include <cuda_runtime.h>
#include <math.h>

#define BB 32
#define NN 32768
#define DD 128
#define TN 128
#define NBLK (NN / TN)   // 256
#define NSLICE 8

typedef unsigned long long u64;

union F4 { float4 v; float f[4]; u64 u[2]; };

// Packed fp32x2 ops (sm_103a FFMA2 — PTX-only)
#define FMA2(d, a, b, c) \
    asm("fma.rn.f32x2 %0, %1, %2, %3;" : "=l"(d) : "l"(a), "l"(b), "l"(c))
#define DUP2(d, v) \
    asm("mov.b64 %0, {%1, %1};" : "=l"(d) : "r"(__float_as_uint(v)))
#define UNPK2(lo, hi, v) \
    asm("mov.b64 {%0, %1}, %2;" : "=f"(lo), "=f"(hi) : "l"(v))

// Scratch
__device__ float g_cm[BB][NBLK];
__device__ float g_cz[BB][NBLK];
__device__ float g_partial[NBLK][BB * DD];        // 4 MB
__device__ float g_p2[NSLICE][BB * DD];           // 128 KB

// smem layout (floats):
//   ys  [128 rows][128], 16B-chunk-swizzled: chunk' = chunk ^ (n&31)   (64 KB)
//   xs  [32][128] natural                                              (16 KB)
//   psD [32 b-rows][128] of u64 {p,p}                                  (32 KB)
//   nrm [128]
#define SM_YS   0
#define SM_XS   16384
#define SM_PSD  20480
#define SM_NRM  28672
#define SMEM_FLOATS 28800
#define SMEM_BYTES  (SMEM_FLOATS * 4)    // 115200 B -> 2 CTAs/SM (230.4KB of 233.5KB)

extern __shared__ float s_mem[];

// ---------------------------------------------------------------------------
// Fused: logits GEMM (k-packed) -> chunk softmax -> weighted-sum GEMM (d-packed)
// Grid: 256 blocks x 256 threads. Warp w owns b = 4w..4w+3.
// ---------------------------------------------------------------------------
__global__ __launch_bounds__(256, 2) void fused_kernel(
    const float* __restrict__ x,       // [B, D]
    const float* __restrict__ alphas,  // [B]
    const float* __restrict__ y)       // [N, D]
{
    float* ys  = s_mem + SM_YS;
    float* xs  = s_mem + SM_XS;
    float* psD = s_mem + SM_PSD;       // viewed as [b][n] u64 dup-pairs
    float* nrm = s_mem + SM_NRM;

    const int tid  = threadIdx.x;
    const int lane = tid & 31;
    const int warp = tid >> 5;
    const int blk  = blockIdx.x;
    const int nbase = blk * TN;

    // ---- x tile (natural layout, float4) ----
#pragma unroll
    for (int it = 0; it < 4; it++) {
        const int i4 = tid + it * 256;
        *(float4*)&xs[i4 * 4] = *(const float4*)&x[i4 * 4];
    }

    // ---- y tile (swizzled float4 stores) + fused |y_n|^2 ----
    // warp-iteration it covers exactly row n = warp + 8*it, chunk t = lane
#pragma unroll
    for (int it = 0; it < 16; it++) {
        const int n = warp + 8 * it;
        F4 q; q.v = *(const float4*)&y[(size_t)(nbase + n) * DD + lane * 4];
        *(float4*)&ys[(n * 32 + (lane ^ (n & 31))) * 4] = q.v;
        float s = q.f[0] * q.f[0] + q.f[1] * q.f[1]
                + q.f[2] * q.f[2] + q.f[3] * q.f[3];
#pragma unroll
        for (int o = 16; o > 0; o >>= 1) s += __shfl_xor_sync(0xffffffffu, s, o);
        if (lane == 0) nrm[n] = s;
    }
    __syncthreads();

    const int b0 = warp * 4;

    // ---- GEMM1 (k-parity packed): acc[i][j] ~ x_{b0+i} . y_{lane+32j} ----
    int rowb[4];
#pragma unroll
    for (int j = 0; j < 4; j++) rowb[j] = (lane + 32 * j) * 128;

    u64 acc[4][4] = {};
#pragma unroll 4
    for (int r = 0; r < 32; r++) {            // r = k/4
        const int off = (r ^ lane) << 2;      // swizzled chunk, shared across j
        F4 yv[4], xv[4];
#pragma unroll
        for (int j = 0; j < 4; j++) yv[j].v = *(const float4*)&ys[rowb[j] + off];
#pragma unroll
        for (int i = 0; i < 4; i++) xv[i].v = *(const float4*)&xs[(b0 + i) * 128 + r * 4];
#pragma unroll
        for (int i = 0; i < 4; i++)
#pragma unroll
            for (int j = 0; j < 4; j++) {
                FMA2(acc[i][j], xv[i].u[0], yv[j].u[0], acc[i][j]);
                FMA2(acc[i][j], xv[i].u[1], yv[j].u[1], acc[i][j]);
            }
    }

    // fold k-parity
    float dots[4][4];
#pragma unroll
    for (int i = 0; i < 4; i++)
#pragma unroll
        for (int j = 0; j < 4; j++) {
            float lo, hi; UNPK2(lo, hi, acc[i][j]);
            dots[i][j] = lo + hi;
        }

    // ---- chunk softmax (warp-private b-rows of psD) ----
    float nv[4];
#pragma unroll
    for (int j = 0; j < 4; j++) nv[j] = nrm[lane + 32 * j];

#pragma unroll
    for (int i = 0; i < 4; i++) {
        const int b = b0 + i;
        const float a   = alphas[b];
        const float var = 1.f - a;
        const float c1  = sqrtf(a) / var;
        const float c2  = a / (2.f * var);
        float l[4];
#pragma unroll
        for (int j = 0; j < 4; j++) l[j] = c1 * dots[i][j] - c2 * nv[j];

        float mi = fmaxf(fmaxf(l[0], l[1]), fmaxf(l[2], l[3]));
#pragma unroll
        for (int o = 16; o > 0; o >>= 1)
            mi = fmaxf(mi, __shfl_xor_sync(0xffffffffu, mi, o));

        float zi = 0.f;
#pragma unroll
        for (int j = 0; j < 4; j++) {
            const float p = __expf(l[j] - mi);
            u64 pd; DUP2(pd, p);
            *(u64*)&psD[b * 256 + (lane + 32 * j) * 2] = pd;   // STS.64 {p,p}
            zi += p;
        }
#pragma unroll
        for (int o = 16; o > 0; o >>= 1) zi += __shfl_xor_sync(0xffffffffu, zi, o);

        if (lane == 0) { g_cm[b][blk] = mi; g_cz[b][blk] = zi; }
    }
    __syncwarp();   // psD rows b0..b0+3 are warp-private

    // ---- GEMM2 (d-packed): acc2[i] covers d = 4*lane..4*lane+3 ----
    u64 acc2[4][2] = {};
#pragma unroll 4
    for (int n = 0; n < TN; n += 2) {
        F4 y0, y1, pp[4];
        y0.v = *(const float4*)&ys[(n * 32       + (lane ^ (n & 31)))       * 4];
        y1.v = *(const float4*)&ys[((n + 1) * 32 + (lane ^ ((n + 1) & 31))) * 4];
#pragma unroll
        for (int i = 0; i < 4; i++)
            pp[i].v = *(const float4*)&psD[(b0 + i) * 256 + n * 2];  // {pn,pn,pn1,pn1} bcast
#pragma unroll
        for (int i = 0; i < 4; i++) {
            FMA2(acc2[i][0], pp[i].u[0], y0.u[0], acc2[i][0]);
            FMA2(acc2[i][1], pp[i].u[0], y0.u[1], acc2[i][1]);
            FMA2(acc2[i][0], pp[i].u[1], y1.u[0], acc2[i][0]);
            FMA2(acc2[i][1], pp[i].u[1], y1.u[1], acc2[i][1]);
        }
    }

    // ---- store partials: STG.128, coalesced ----
#pragma unroll
    for (int i = 0; i < 4; i++) {
        F4 o; o.u[0] = acc2[i][0]; o.u[1] = acc2[i][1];
        *(float4*)&g_partial[blk][(b0 + i) * DD + 4 * lane] = o.v;
    }
}

// ---------------------------------------------------------------------------
// Reduce: 256 blocks (b x 8 slices) x 256 threads.
// ---------------------------------------------------------------------------
__global__ __launch_bounds__(256) void reduce_kernel()
{
    const int slice = blockIdx.x & 7;
    const int b     = blockIdx.x >> 3;
    const int tid   = threadIdx.x;
    const int lane  = tid & 31;
    const int warp  = tid >> 5;

    __shared__ float wv[NBLK];
    __shared__ float red[8];
    __shared__ float part[2][DD];
    __shared__ float Msh;

    const float cm = g_cm[b][tid];
    float m = cm;
#pragma unroll
    for (int o = 16; o > 0; o >>= 1) m = fmaxf(m, __shfl_xor_sync(0xffffffffu, m, o));
    if (lane == 0) red[warp] = m;
    __syncthreads();
    if (tid == 0) {
        float v = red[0];
        for (int w = 1; w < 8; w++) v = fmaxf(v, red[w]);
        Msh = v;
    }
    __syncthreads();

    wv[tid] = __expf(cm - Msh);
    __syncthreads();

    const int d = tid & 127;
    const int g = tid >> 7;
    float s = 0.f;
#pragma unroll
    for (int i = 0; i < 16; i++) {
        const int c = slice * 32 + g + 2 * i;
        s += g_partial[c][b * DD + d] * wv[c];
    }
    part[g][d] = s;
    __syncthreads();
    if (tid < DD) g_p2[slice][b * DD + tid] = part[0][tid] + part[1][tid];
}

// ---------------------------------------------------------------------------
// Final: 32 blocks x 128 threads.
// ---------------------------------------------------------------------------
__global__ __launch_bounds__(128) void final_kernel(
    const float* __restrict__ x,
    const float* __restrict__ alphas,
    float* __restrict__ out)
{
    const int b    = blockIdx.x;
    const int tid  = threadIdx.x;
    const int lane = tid & 31;
    const int warp = tid >> 5;

    __shared__ float red[4];
    __shared__ float Msh, Zsh;

    const float cm0 = g_cm[b][tid], cm1 = g_cm[b][tid + 128];
    float m = fmaxf(cm0, cm1);
#pragma unroll
    for (int o = 16; o > 0; o >>= 1) m = fmaxf(m, __shfl_xor_sync(0xffffffffu, m, o));
    if (lane == 0) red[warp] = m;
    __syncthreads();
    if (tid == 0) Msh = fmaxf(fmaxf(red[0], red[1]), fmaxf(red[2], red[3]));
    __syncthreads();
    const float M = Msh;

    float z = g_cz[b][tid] * __expf(cm0 - M) + g_cz[b][tid + 128] * __expf(cm1 - M);
#pragma unroll
    for (int o = 16; o > 0; o >>= 1) z += __shfl_xor_sync(0xffffffffu, z, o);
    __syncthreads();
    if (lane == 0) red[warp] = z;
    __syncthreads();
    if (tid == 0) Zsh = red[0] + red[1] + red[2] + red[3];
    __syncthreads();

    float s = 0.f;
#pragma unroll
    for (int c = 0; c < NSLICE; c++) s += g_p2[c][b * DD + tid];

    const float a   = alphas[b];
    const float var = 1.f - a;
    const float x0  = s / Zsh;
    out[b * DD + tid] = (x[b * DD + tid] - sqrtf(a) * x0) / sqrtf(var);
}

// ---------------------------------------------------------------------------
extern "C" void kernel_launch(void* const* d_in, const int* in_sizes, int n_in,
                              void* d_out, int out_size)
{
    const float* inputs = (const float*)d_in[0];
    const float* alphas = (const float*)d_in[1];
    const float* data   = (const float*)d_in[2];
    float* out = (float*)d_out;

    cudaFuncSetAttribute(fused_kernel,
                         cudaFuncAttributeMaxDynamicSharedMemorySize, SMEM_BYTES);

    fused_kernel<<<NBLK, 256, SMEM_BYTES>>>(inputs, alphas, data);
    reduce_kernel<<<BB * NSLICE, 256>>>();
    final_kernel<<<BB, DD>>>(inputs, alphas, out);
}